// round 3
// baseline (speedup 1.0000x reference)
#include <cuda_runtime.h>
#include <cuda_bf16.h>
#include <cstdint>

#define B_ 2
#define S_ 2048
#define D_ 256
#define H_ 8

// Scratch (no allocations allowed -> static device globals)
__device__ float g_Q[(size_t)B_ * H_ * S_ * D_];   // 32 MB
__device__ float g_K[(size_t)B_ * H_ * S_ * D_];   // 32 MB
__device__ float g_V[(size_t)B_ * H_ * S_ * D_];   // 32 MB
__device__ float g_P[(size_t)B_ * H_ * S_ * S_];   // 256 MB (scores -> probs in place)
__device__ float g_O[(size_t)B_ * S_ * H_ * D_];   // 32 MB, [B,S,H,D] for contiguous final GEMM

// round-to-nearest tf32 (unbiased; truncation would bias results ~7e-4)
__device__ __forceinline__ float f2tf32(float x) {
    uint32_t r;
    asm("cvt.rna.tf32.f32 %0, %1;" : "=r"(r) : "f"(x));
    return __uint_as_float(r);
}

__device__ __forceinline__ void mma_tf32(float* c, const uint32_t* a, const uint32_t* b) {
    asm volatile(
        "mma.sync.aligned.m16n8k8.row.col.f32.tf32.tf32.f32 "
        "{%0,%1,%2,%3}, {%4,%5,%6,%7}, {%8,%9}, {%0,%1,%2,%3};"
        : "+f"(c[0]), "+f"(c[1]), "+f"(c[2]), "+f"(c[3])
        : "r"(a[0]), "r"(a[1]), "r"(a[2]), "r"(a[3]), "r"(b[0]), "r"(b[1]));
}

// ---------------------------------------------------------------------------
// 128x128 CTA tile GEMM on tf32 tensor cores. 256 threads = 8 warps in a
// 2(m) x 4(n) grid; each warp owns 64x32 via m16n8k8 atoms. BK=16.
// smem holds fragment-permuted tiles: each thread's A-frag is one lds.128,
// B-frag one lds.64 (conflict-free). Double-buffered + register prefetch.
// TB=false: C = A[M,K] * B[K,N] ; TB=true: C = A[M,K] * B[N,K]^T
// ---------------------------------------------------------------------------
template <bool TB>
__device__ __forceinline__ void gemm_mma(const float* __restrict__ A,
                                         const float* __restrict__ Bm,
                                         float* __restrict__ C,
                                         int K, int lda, int ldb, int ldc,
                                         float scale, int mtile)
{
    __shared__ float As[2][2048];   // [kt(2)][matom(8)][lane(32)][r(4)]
    __shared__ float Bs[2][2048];   // [kt(2)][natom(16)][lane(32)][r(2)]

    const int t    = threadIdx.x;
    const int lane = t & 31;
    const int wid  = t >> 5;
    const int wm   = wid >> 2;      // 0..1 : warp row (64 rows)
    const int wn   = wid & 3;       // 0..3 : warp col (32 cols)
    const int m0   = mtile * 128;
    const int n0   = blockIdx.y * 128;

    // --- loader index precompute (2 float4 per thread per tile) ---
    // A tile: [128 rows][16 k] ; TB B tile has the same shape over n-rows.
    int aRow[2], aC4[2];
    #pragma unroll
    for (int i = 0; i < 2; i++) {
        int idx = t + i * 256;
        aRow[i] = idx >> 2;
        aC4[i]  = (idx & 3) * 4;
    }
    // B NN tile: [16 k][128 n]
    int bK[2], bN4[2];
    #pragma unroll
    for (int i = 0; i < 2; i++) {
        int idx = t + i * 256;
        bK[i]  = idx >> 5;
        bN4[i] = (idx & 31) * 4;
    }

    const float* pA[2];
    const float* pB[2];
    #pragma unroll
    for (int i = 0; i < 2; i++) {
        pA[i] = A + (size_t)(m0 + aRow[i]) * lda + aC4[i];
        pB[i] = TB ? (Bm + (size_t)(n0 + aRow[i]) * ldb + aC4[i])
                   : (Bm + (size_t)bK[i] * ldb + n0 + bN4[i]);
    }

    float4 ra[2], rb[2];
    auto load_regs = [&]() {
        ra[0] = *(const float4*)pA[0];
        ra[1] = *(const float4*)pA[1];
        rb[0] = *(const float4*)pB[0];
        rb[1] = *(const float4*)pB[1];
    };

    auto store_stage = [&](int buf) {
        #pragma unroll
        for (int i = 0; i < 2; i++) {
            // A scatter: (row, k) -> perm
            int row = aRow[i];
            int matom = row >> 4;
            int g  = row & 7;
            int rh = (row >> 3) & 1;
            float v[4] = {ra[i].x, ra[i].y, ra[i].z, ra[i].w};
            #pragma unroll
            for (int f = 0; f < 4; f++) {
                int k   = aC4[i] + f;
                int kt  = k >> 3;
                int kk  = k & 7;
                int r   = rh + ((kk >> 2) << 1);
                int c   = kk & 3;
                As[buf][(((kt << 3) + matom) * 32 + (g << 2) + c) * 4 + r] = f2tf32(v[f]);
            }
            // B scatter
            float w[4] = {rb[i].x, rb[i].y, rb[i].z, rb[i].w};
            if (TB) {
                int n     = aRow[i];
                int natom = n >> 3;
                int gg    = n & 7;
                #pragma unroll
                for (int f = 0; f < 4; f++) {
                    int k  = aC4[i] + f;
                    int kt = k >> 3;
                    int kk = k & 7;
                    int r  = kk >> 2;
                    int c  = kk & 3;
                    Bs[buf][(((kt << 4) + natom) * 32 + (gg << 2) + c) * 2 + r] = f2tf32(w[f]);
                }
            } else {
                int k  = bK[i];
                int kt = k >> 3;
                int kk = k & 7;
                int r  = kk >> 2;
                int c  = kk & 3;
                #pragma unroll
                for (int f = 0; f < 4; f++) {
                    int n     = bN4[i] + f;
                    int natom = n >> 3;
                    int gg    = n & 7;
                    Bs[buf][(((kt << 4) + natom) * 32 + (gg << 2) + c) * 2 + r] = f2tf32(w[f]);
                }
            }
        }
    };

    float acc[4][4][4] = {};   // [matom][natom][c-frag]

    auto compute_stage = [&](int buf) {
        #pragma unroll
        for (int kt = 0; kt < 2; kt++) {
            uint32_t a[4][4], b[4][2];
            #pragma unroll
            for (int i = 0; i < 4; i++) {
                float4 v = *(const float4*)&As[buf][(((kt << 3) + (wm << 2) + i) * 32 + lane) * 4];
                a[i][0] = __float_as_uint(v.x); a[i][1] = __float_as_uint(v.y);
                a[i][2] = __float_as_uint(v.z); a[i][3] = __float_as_uint(v.w);
            }
            #pragma unroll
            for (int j = 0; j < 4; j++) {
                float2 v = *(const float2*)&Bs[buf][(((kt << 4) + (wn << 2) + j) * 32 + lane) * 2];
                b[j][0] = __float_as_uint(v.x); b[j][1] = __float_as_uint(v.y);
            }
            #pragma unroll
            for (int i = 0; i < 4; i++)
                #pragma unroll
                for (int j = 0; j < 4; j++)
                    mma_tf32(acc[i][j], a[i], b[j]);
        }
    };

    // Prologue
    load_regs();
    store_stage(0);
    __syncthreads();

    int buf = 0;
    for (int k0 = 16; k0 < K; k0 += 16) {
        #pragma unroll
        for (int i = 0; i < 2; i++) {
            pA[i] += 16;
            pB[i] += TB ? 16 : (size_t)16 * ldb;
        }
        load_regs();              // prefetch next stage (hidden by MMA)
        compute_stage(buf);
        __syncthreads();
        store_stage(buf ^ 1);
        __syncthreads();
        buf ^= 1;
    }
    compute_stage(buf);

    // Epilogue: c-frag layout of m16n8: (g, 2c), (g, 2c+1), (g+8, ...)
    const int g = lane >> 2;
    const int c = lane & 3;
    #pragma unroll
    for (int i = 0; i < 4; i++) {
        #pragma unroll
        for (int j = 0; j < 4; j++) {
            int row = m0 + wm * 64 + i * 16 + g;
            int col = n0 + wn * 32 + j * 8 + c * 2;
            float2 lo = {acc[i][j][0] * scale, acc[i][j][1] * scale};
            float2 hi = {acc[i][j][2] * scale, acc[i][j][3] * scale};
            *(float2*)(C + (size_t)row * ldc + col)       = lo;
            *(float2*)(C + (size_t)(row + 8) * ldc + col) = hi;
        }
    }
}

// ---------------------------------------------------------------------------
// 1) Q/K/V projections
// ---------------------------------------------------------------------------
__global__ __launch_bounds__(256, 2) void proj_kernel(const float* __restrict__ x,
                                                      const float* __restrict__ wQ,
                                                      const float* __restrict__ wK,
                                                      const float* __restrict__ wV)
{
    const int z     = blockIdx.z;
    const int which = z / (B_ * H_);
    const int bh    = z % (B_ * H_);
    const int b     = bh / H_;
    const int h     = bh % H_;

    const float* A = x + (size_t)b * S_ * D_;
    const float* W = (which == 0 ? wQ : which == 1 ? wK : wV) + (size_t)h * D_ * D_;
    float* C = (which == 0 ? g_Q : which == 1 ? g_K : g_V) + (size_t)bh * S_ * D_;

    gemm_mma<false>(A, W, C, D_, D_, D_, D_, 1.0f, blockIdx.x);
}

// ---------------------------------------------------------------------------
// 2) Scores = Q @ K^T / sqrt(D); skip tiles strictly above the diagonal
// ---------------------------------------------------------------------------
__global__ __launch_bounds__(256, 2) void qk_kernel()
{
    if (blockIdx.y > blockIdx.x) return;
    const int bh = blockIdx.z;
    const float* A  = g_Q + (size_t)bh * S_ * D_;
    const float* Bm = g_K + (size_t)bh * S_ * D_;
    float* C = g_P + (size_t)bh * S_ * S_;
    gemm_mma<true>(A, Bm, C, D_, D_, D_, S_, 0.0625f, blockIdx.x);
}

// ---------------------------------------------------------------------------
// 3) Causal softmax, one block per row; zero-fills j>i so PV is dense
// ---------------------------------------------------------------------------
__global__ void softmax_kernel()
{
    const int i  = blockIdx.x;
    const int bh = blockIdx.y;
    float* row = g_P + ((size_t)bh * S_ + i) * S_;
    const int len = i + 1;
    const int t = threadIdx.x;
    __shared__ float red[8];

    float m = -3.402823e38f;
    for (int j = t; j < len; j += 256) m = fmaxf(m, row[j]);
    #pragma unroll
    for (int o = 16; o; o >>= 1) m = fmaxf(m, __shfl_xor_sync(0xffffffffu, m, o));
    if ((t & 31) == 0) red[t >> 5] = m;
    __syncthreads();
    m = red[0];
    #pragma unroll
    for (int w = 1; w < 8; w++) m = fmaxf(m, red[w]);
    __syncthreads();

    float s = 0.0f;
    for (int j = t; j < len; j += 256) {
        float e = __expf(row[j] - m);
        row[j] = e;
        s += e;
    }
    #pragma unroll
    for (int o = 16; o; o >>= 1) s += __shfl_xor_sync(0xffffffffu, s, o);
    if ((t & 31) == 0) red[t >> 5] = s;
    __syncthreads();
    float tot = red[0];
    #pragma unroll
    for (int w = 1; w < 8; w++) tot += red[w];
    const float inv = 1.0f / tot;

    for (int j = t; j < len; j += 256) row[j] *= inv;
    for (int j = len + t; j < S_; j += 256) row[j] = 0.0f;
}

// ---------------------------------------------------------------------------
// 4) O = P @ V, K truncated at causal boundary; heavy tiles first
// ---------------------------------------------------------------------------
__global__ __launch_bounds__(256, 2) void pv_kernel()
{
    const int bh = blockIdx.z;
    const int b  = bh / H_;
    const int h  = bh % H_;
    const int mtile = gridDim.x - 1 - blockIdx.x;
    const int Keff = (mtile + 1) * 128;
    const float* A  = g_P + (size_t)bh * S_ * S_;
    const float* Bm = g_V + (size_t)bh * S_ * D_;
    float* C = g_O + (size_t)b * S_ * H_ * D_ + (size_t)h * D_;
    gemm_mma<false>(A, Bm, C, Keff, S_, D_, H_ * D_, 1.0f, mtile);
}

// ---------------------------------------------------------------------------
// 5) out[B*S, D] = g_O[B*S, H*D] @ wO[H*D, D]
// ---------------------------------------------------------------------------
__global__ __launch_bounds__(256, 2) void out_kernel(const float* __restrict__ wO,
                                                     float* __restrict__ out)
{
    gemm_mma<false>(g_O, wO, out, H_ * D_, H_ * D_, D_, D_, 1.0f, blockIdx.x);
}

// ---------------------------------------------------------------------------
extern "C" void kernel_launch(void* const* d_in, const int* in_sizes, int n_in,
                              void* d_out, int out_size)
{
    const float* x  = (const float*)d_in[0];
    // d_in[1] = timestamp (dead code in reference)
    const float* wQ = (const float*)d_in[2];
    const float* wK = (const float*)d_in[3];
    const float* wV = (const float*)d_in[4];
    const float* wO = (const float*)d_in[5];
    // d_in[6] = theta (dead code)
    float* out = (float*)d_out;

    dim3 blk(256);
    proj_kernel<<<dim3(S_ / 128, D_ / 128, 3 * B_ * H_), blk>>>(x, wQ, wK, wV);
    qk_kernel<<<dim3(S_ / 128, S_ / 128, B_ * H_), blk>>>();
    softmax_kernel<<<dim3(S_, B_ * H_), blk>>>();
    pv_kernel<<<dim3(S_ / 128, D_ / 128, B_ * H_), blk>>>();
    out_kernel<<<dim3(B_ * S_ / 128, D_ / 128, 1), blk>>>(wO, out);
}

// round 6
// speedup vs baseline: 2.4022x; 2.4022x over previous
#include <cuda_runtime.h>
#include <cuda_bf16.h>
#include <cstdint>

#define B_ 2
#define S_ 2048
#define D_ 256
#define H_ 8

// Scratch (no allocations allowed -> static device globals)
__device__ float g_Q[(size_t)B_ * H_ * S_ * D_];   // tf32-rounded
__device__ float g_K[(size_t)B_ * H_ * S_ * D_];   // tf32-rounded
__device__ float g_V[(size_t)B_ * H_ * S_ * D_];   // tf32-rounded
__device__ float g_P[(size_t)B_ * H_ * S_ * S_];   // scores (raw) -> probs (tf32-rounded)
__device__ float g_O[(size_t)B_ * S_ * H_ * D_];   // raw fp32 [B,S,H,D]

// round-to-nearest tf32 (unbiased)
__device__ __forceinline__ float f2tf32(float x) {
    uint32_t r;
    asm("cvt.rna.tf32.f32 %0, %1;" : "=r"(r) : "f"(x));
    return __uint_as_float(r);
}

__device__ __forceinline__ void mma_tf32(float* c, const uint32_t* a, const uint32_t* b) {
    asm volatile(
        "mma.sync.aligned.m16n8k8.row.col.f32.tf32.tf32.f32 "
        "{%0,%1,%2,%3}, {%4,%5,%6,%7}, {%8,%9}, {%0,%1,%2,%3};"
        : "+f"(c[0]), "+f"(c[1]), "+f"(c[2]), "+f"(c[3])
        : "r"(a[0]), "r"(a[1]), "r"(a[2]), "r"(a[3]), "r"(b[0]), "r"(b[1]));
}

__device__ __forceinline__ void cpa16(uint32_t dst, const void* src) {
    asm volatile("cp.async.cg.shared.global [%0], [%1], 16;" :: "r"(dst), "l"(src));
}
__device__ __forceinline__ void cpa_commit() { asm volatile("cp.async.commit_group;"); }

#define SA_STRIDE 20     // 16 data + 4 pad floats: g*20+c bijective mod 32 banks
#define SBN_STRIDE 136   // 128 data + 8 pad: c*8+g bijective mod 32 banks

// ---------------------------------------------------------------------------
// 128x128 CTA tile tf32 tensor-core GEMM, 256 threads = 8 warps (2m x 4n),
// each warp 64x32 via m16n8k8. BK=16, cp.async double-buffered canonical smem
// with conflict-free padded strides, per-value LDS on the compute side.
// TB=false: C = A[M,K] * B[K,N] ; TB=true: C = A[M,K] * B[N,K]^T
// CVTL: round loads to tf32 (for external fp32 inputs). CVTS: round stores.
// ---------------------------------------------------------------------------
template <bool TB, bool CVTL, bool CVTS>
__device__ __forceinline__ void gemm_cp(const float* __restrict__ A,
                                        const float* __restrict__ Bm,
                                        float* __restrict__ C,
                                        int K, int lda, int ldb, int ldc,
                                        float scale, int mtile)
{
    __shared__ float As[2][128 * SA_STRIDE];   // 10 KB per stage
    __shared__ float Bs[2][128 * SA_STRIDE];   // sized for worst case (TB)

    const int t    = threadIdx.x;
    const int lane = t & 31;
    const int wid  = t >> 5;
    const int wm   = wid >> 2;      // 0..1
    const int wn   = wid & 3;       // 0..3
    const int g    = lane >> 2;     // 0..7
    const int c    = lane & 3;      // 0..3
    const int m0   = mtile * 128;
    const int n0   = blockIdx.y * 128;

    const uint32_t sA0 = (uint32_t)__cvta_generic_to_shared(&As[0][0]);
    const uint32_t sA1 = (uint32_t)__cvta_generic_to_shared(&As[1][0]);
    const uint32_t sB0 = (uint32_t)__cvta_generic_to_shared(&Bs[0][0]);
    const uint32_t sB1 = (uint32_t)__cvta_generic_to_shared(&Bs[1][0]);

    // loader indices: 2 x 16B chunks for A, 2 for B
    const int aRow0 = t >> 2,            aC0 = (t & 3) * 4;
    const int aRow1 = (t + 256) >> 2,    aC1 = aC0;
    // NN B: [16][128]
    const int bK0 = t >> 5,              bN0 = (t & 31) * 4;
    const int bK1 = (t + 256) >> 5,      bN1 = bN0;

    auto issue_stage = [&](int k0, int buf) {
        const uint32_t sa = buf ? sA1 : sA0;
        const uint32_t sb = buf ? sB1 : sB0;
        cpa16(sa + (aRow0 * SA_STRIDE + aC0) * 4, A + (size_t)(m0 + aRow0) * lda + k0 + aC0);
        cpa16(sa + (aRow1 * SA_STRIDE + aC1) * 4, A + (size_t)(m0 + aRow1) * lda + k0 + aC1);
        if (TB) {
            cpa16(sb + (aRow0 * SA_STRIDE + aC0) * 4, Bm + (size_t)(n0 + aRow0) * ldb + k0 + aC0);
            cpa16(sb + (aRow1 * SA_STRIDE + aC1) * 4, Bm + (size_t)(n0 + aRow1) * ldb + k0 + aC1);
        } else {
            cpa16(sb + (bK0 * SBN_STRIDE + bN0) * 4, Bm + (size_t)(k0 + bK0) * ldb + n0 + bN0);
            cpa16(sb + (bK1 * SBN_STRIDE + bN1) * 4, Bm + (size_t)(k0 + bK1) * ldb + n0 + bN1);
        }
        cpa_commit();
    };

    float acc[4][4][4] = {};   // [matom][natom][cfrag]

    auto ldval = [&](const float* p) -> uint32_t {
        float v = *p;
        if (CVTL) v = f2tf32(v);
        return __float_as_uint(v);
    };

    auto compute_stage = [&](int buf) {
        const float* as = As[buf];
        const float* bs = Bs[buf];
        #pragma unroll
        for (int kt = 0; kt < 2; kt++) {
            uint32_t a[4][4], b[4][2];
            #pragma unroll
            for (int i = 0; i < 4; i++) {
                const int row = wm * 64 + i * 16 + g;
                const int base = row * SA_STRIDE + kt * 8 + c;
                a[i][0] = ldval(as + base);
                a[i][1] = ldval(as + base + 8 * SA_STRIDE);
                a[i][2] = ldval(as + base + 4);
                a[i][3] = ldval(as + base + 8 * SA_STRIDE + 4);
            }
            #pragma unroll
            for (int j = 0; j < 4; j++) {
                if (TB) {
                    const int base = (wn * 32 + j * 8 + g) * SA_STRIDE + kt * 8 + c;
                    b[j][0] = ldval(bs + base);
                    b[j][1] = ldval(bs + base + 4);
                } else {
                    const int base = (kt * 8 + c) * SBN_STRIDE + wn * 32 + j * 8 + g;
                    b[j][0] = ldval(bs + base);
                    b[j][1] = ldval(bs + base + 4 * SBN_STRIDE);
                }
            }
            #pragma unroll
            for (int i = 0; i < 4; i++)
                #pragma unroll
                for (int j = 0; j < 4; j++)
                    mma_tf32(acc[i][j], a[i], b[j]);
        }
    };

    const int KS = K >> 4;
    issue_stage(0, 0);
    for (int ks = 0; ks < KS; ks++) {
        if (ks + 1 < KS) {
            issue_stage((ks + 1) << 4, (ks + 1) & 1);
            asm volatile("cp.async.wait_group 1;");
        } else {
            asm volatile("cp.async.wait_group 0;");
        }
        __syncthreads();
        compute_stage(ks & 1);
        __syncthreads();   // protect buffer reuse by next iteration's issue
    }

    // Epilogue: m16n8 c-frag -> (g,2c),(g,2c+1) and (g+8,...)
    #pragma unroll
    for (int i = 0; i < 4; i++) {
        #pragma unroll
        for (int j = 0; j < 4; j++) {
            const int row = m0 + wm * 64 + i * 16 + g;
            const int col = n0 + wn * 32 + j * 8 + c * 2;
            float2 lo = {acc[i][j][0] * scale, acc[i][j][1] * scale};
            float2 hi = {acc[i][j][2] * scale, acc[i][j][3] * scale};
            if (CVTS) {
                lo.x = f2tf32(lo.x); lo.y = f2tf32(lo.y);
                hi.x = f2tf32(hi.x); hi.y = f2tf32(hi.y);
            }
            *(float2*)(C + (size_t)row * ldc + col)       = lo;
            *(float2*)(C + (size_t)(row + 8) * ldc + col) = hi;
        }
    }
}

// ---------------------------------------------------------------------------
// 1) Q/K/V projections (external fp32 in -> tf32-rounded out)
// ---------------------------------------------------------------------------
__global__ __launch_bounds__(256, 2) void proj_kernel(const float* __restrict__ x,
                                                      const float* __restrict__ wQ,
                                                      const float* __restrict__ wK,
                                                      const float* __restrict__ wV)
{
    const int z     = blockIdx.z;
    const int which = z / (B_ * H_);
    const int bh    = z % (B_ * H_);
    const int b     = bh / H_;
    const int h     = bh % H_;

    const float* A = x + (size_t)b * S_ * D_;
    const float* W = (which == 0 ? wQ : which == 1 ? wK : wV) + (size_t)h * D_ * D_;
    float* C = (which == 0 ? g_Q : which == 1 ? g_K : g_V) + (size_t)bh * S_ * D_;

    gemm_cp<false, true, true>(A, W, C, D_, D_, D_, D_, 1.0f, blockIdx.x);
}

// ---------------------------------------------------------------------------
// 2) Scores = Q @ K^T / sqrt(D); inputs pre-rounded, raw fp32 scores out
// ---------------------------------------------------------------------------
__global__ __launch_bounds__(256, 2) void qk_kernel()
{
    if (blockIdx.y > blockIdx.x) return;
    const int bh = blockIdx.z;
    const float* A  = g_Q + (size_t)bh * S_ * D_;
    const float* Bm = g_K + (size_t)bh * S_ * D_;
    float* C = g_P + (size_t)bh * S_ * S_;
    gemm_cp<true, false, false>(A, Bm, C, D_, D_, D_, S_, 0.0625f, blockIdx.x);
}

// ---------------------------------------------------------------------------
// 3) Causal softmax; writes tf32-rounded probs, zero-fills j>i
// ---------------------------------------------------------------------------
__global__ void softmax_kernel()
{
    const int i  = blockIdx.x;
    const int bh = blockIdx.y;
    float* row = g_P + ((size_t)bh * S_ + i) * S_;
    const int len = i + 1;
    const int t = threadIdx.x;
    __shared__ float red[8];

    float m = -3.402823e38f;
    for (int j = t; j < len; j += 256) m = fmaxf(m, row[j]);
    #pragma unroll
    for (int o = 16; o; o >>= 1) m = fmaxf(m, __shfl_xor_sync(0xffffffffu, m, o));
    if ((t & 31) == 0) red[t >> 5] = m;
    __syncthreads();
    m = red[0];
    #pragma unroll
    for (int w = 1; w < 8; w++) m = fmaxf(m, red[w]);
    __syncthreads();

    float s = 0.0f;
    for (int j = t; j < len; j += 256) {
        float e = __expf(row[j] - m);
        row[j] = e;
        s += e;
    }
    #pragma unroll
    for (int o = 16; o; o >>= 1) s += __shfl_xor_sync(0xffffffffu, s, o);
    if ((t & 31) == 0) red[t >> 5] = s;
    __syncthreads();
    float tot = red[0];
    #pragma unroll
    for (int w = 1; w < 8; w++) tot += red[w];
    const float inv = 1.0f / tot;

    for (int j = t; j < len; j += 256) row[j] = f2tf32(row[j] * inv);
    for (int j = len + t; j < S_; j += 256) row[j] = 0.0f;
}

// ---------------------------------------------------------------------------
// 4) O = P @ V, K truncated at causal boundary; heavy tiles first
// ---------------------------------------------------------------------------
__global__ __launch_bounds__(256, 2) void pv_kernel()
{
    const int bh = blockIdx.z;
    const int b  = bh / H_;
    const int h  = bh % H_;
    const int mtile = gridDim.x - 1 - blockIdx.x;
    const int Keff = (mtile + 1) * 128;
    const float* A  = g_P + (size_t)bh * S_ * S_;
    const float* Bm = g_V + (size_t)bh * S_ * D_;
    float* C = g_O + (size_t)b * S_ * H_ * D_ + (size_t)h * D_;
    gemm_cp<false, false, false>(A, Bm, C, Keff, S_, D_, H_ * D_, 1.0f, mtile);
}

// ---------------------------------------------------------------------------
// 5) out[B*S, D] = g_O[B*S, H*D] @ wO[H*D, D]  (raw fp32 inputs -> cvt on load)
// ---------------------------------------------------------------------------
__global__ __launch_bounds__(256, 2) void out_kernel(const float* __restrict__ wO,
                                                     float* __restrict__ out)
{
    gemm_cp<false, true, false>(g_O, wO, out, H_ * D_, H_ * D_, D_, D_, 1.0f, blockIdx.x);
}

// ---------------------------------------------------------------------------
extern "C" void kernel_launch(void* const* d_in, const int* in_sizes, int n_in,
                              void* d_out, int out_size)
{
    const float* x  = (const float*)d_in[0];
    // d_in[1] = timestamp (dead code in reference)
    const float* wQ = (const float*)d_in[2];
    const float* wK = (const float*)d_in[3];
    const float* wV = (const float*)d_in[4];
    const float* wO = (const float*)d_in[5];
    // d_in[6] = theta (dead code)
    float* out = (float*)d_out;

    dim3 blk(256);
    proj_kernel<<<dim3(S_ / 128, D_ / 128, 3 * B_ * H_), blk>>>(x, wQ, wK, wV);
    qk_kernel<<<dim3(S_ / 128, S_ / 128, B_ * H_), blk>>>();
    softmax_kernel<<<dim3(S_, B_ * H_), blk>>>();
    pv_kernel<<<dim3(S_ / 128, D_ / 128, B_ * H_), blk>>>();
    out_kernel<<<dim3(B_ * S_ / 128, D_ / 128, 1), blk>>>(wO, out);
}